// round 7
// baseline (speedup 1.0000x reference)
#include <cuda_runtime.h>
#include <cuda_bf16.h>
#include <math.h>

#define Bn 16
#define Nn 2048
#define Fn 64
#define Tn 32
#define CHUNKS 128             // chunks (blocks) per batch
#define NC (Nn / CHUNKS)       // 16 nodes per chunk
#define NBLK (Bn * CHUNKS)     // 2048 blocks

// Partial accumulators: [block][0=lhs1,1=R2][f*t]  (32 MB)
__device__ float g_partial[NBLK][2][Fn * Tn];
// Per-batch arrival counters (zero-init; reset by the winning block each run)
__device__ int g_counter[Bn];

// ---------------------------------------------------------------------------
// Single fused kernel.
//   Main phase (identical to the measured-fast R4/R6 loop): stream x once,
//   barrier-free over 16 nodes, one barrier, cross-warp r-reduction, R2 acc.
//   Tail phase: the LAST block to finish within each batch sums that batch's
//   128 partials (L2-hot) and computes the full epilogue for the batch.
// ---------------------------------------------------------------------------
__global__ __launch_bounds__(256, 5)
void fused_kernel(const float* __restrict__ x,
                  const float* __restrict__ U1,
                  const float* __restrict__ U2,
                  const float* __restrict__ U3,
                  const float* __restrict__ b_e,
                  const float* __restrict__ V_e,
                  float* __restrict__ out)
{
    const int blk  = blockIdx.x;        // 0..NBLK-1
    const int b    = blk >> 7;          // / CHUNKS
    const int c    = blk & (CHUNKS - 1);
    const int n0   = c * NC;
    const int tid  = threadIdx.x;
    const int w    = tid >> 5;          // warp 0..7
    const int lane = tid & 31;          // = t

    // One raw smem arena, aliased by phase.
    __shared__ __align__(16) char smem_raw[24 * 1024];
    // Phase-1 layout (22.5 KB used):
    float (*red)[8][32] = (float (*)[8][32])(smem_raw);              // 16 KB
    float (*U2s)[Fn]    = (float (*)[Fn])(smem_raw + 16 * 1024);     // 4 KB
    float *U3s          = (float *)(smem_raw + 20 * 1024);           // 256 B
    float *U1s          = (float *)(smem_raw + 20 * 1024 + 256);     // 64 B
    float (*rsum)[32]   = (float (*)[32])(smem_raw + 20 * 1024 + 512); // 2 KB

    if (tid < Fn) U3s[tid] = U3[tid];
    if (tid < NC) U1s[tid] = U1[n0 + tid];
    for (int i = tid; i < NC * Fn; i += 256) {
        int f  = i >> 4;                // i / NC  (NC == 16)
        int nn = i & (NC - 1);
        U2s[nn][f] = U2[f * Nn + n0 + nn];
    }
    __syncthreads();

    float accL[8];
#pragma unroll
    for (int j = 0; j < 8; j++) accL[j] = 0.f;

    const float* xb = x + ((size_t)b * Nn + n0) * (Fn * Tn);
    const int fbase = w * 8;
    float u3r[8];
#pragma unroll
    for (int j = 0; j < 8; j++) u3r[j] = U3s[fbase + j];

    // ---- Phase A: barrier-free streaming over 16 nodes ----
#pragma unroll 2
    for (int nn = 0; nn < NC; nn++) {
        const float* xn = xb + (size_t)nn * (Fn * Tn) + fbase * Tn + lane;
        float v[8];
#pragma unroll
        for (int j = 0; j < 8; j++)
            v[j] = xn[j * Tn];

        const float u1n = U1s[nn];
        float r = 0.f;
#pragma unroll
        for (int j = 0; j < 8; j++) {
            accL[j] = fmaf(u1n, v[j], accL[j]);
            r = fmaf(u3r[j], v[j], r);
        }
        red[nn][w][lane] = r;
    }
    __syncthreads();

    // ---- Phase B: reduce r across warps, then R2 accumulation ----
#pragma unroll
    for (int h = 0; h < 2; h++) {
        int i  = tid + h * 256;
        int nn = i >> 5;
        int t  = i & 31;
        float s = 0.f;
#pragma unroll
        for (int w2 = 0; w2 < 8; w2++) s += red[i >> 5][w2][t];
        rsum[nn][t] = s;
    }
    __syncthreads();

    float accR[8];
#pragma unroll
    for (int j = 0; j < 8; j++) accR[j] = 0.f;
#pragma unroll
    for (int nn = 0; nn < NC; nn++) {
        const float rt = rsum[nn][lane];
#pragma unroll
        for (int j = 0; j < 8; j++)
            accR[j] = fmaf(U2s[nn][fbase + j], rt, accR[j]);
    }

    {
        float* pl = &g_partial[blk][0][0];
        float* pr = &g_partial[blk][1][0];
#pragma unroll
        for (int j = 0; j < 8; j++) {
            pl[(fbase + j) * Tn + lane] = accL[j];
            pr[(fbase + j) * Tn + lane] = accR[j];
        }
    }

    // ---- Arrival protocol: last block of this batch runs the epilogue ----
    __threadfence();
    __shared__ int s_last;
    if (tid == 0) {
        int old = atomicAdd(&g_counter[b], 1);
        s_last = (old == CHUNKS - 1);
        if (s_last) g_counter[b] = 0;   // reset for the next graph replay
    }
    __syncthreads();
    if (!s_last) return;

    // ================= Epilogue (one block per batch) =================
    // Re-alias smem: LsRs[4096] @0 (16 KB), sig[1024] @16K, VeT[1024] @20K.
    float *LsRs = (float *)(smem_raw);
    float *sig  = (float *)(smem_raw + 16 * 1024);
    float *VeT  = (float *)(smem_raw + 20 * 1024);

    // Sum 128 partials: 1024 float4 outputs, 4 per thread, L2-hot reads.
    const float4* pbase = (const float4*)(&g_partial[b * CHUNKS][0][0]);
#pragma unroll
    for (int h = 0; h < 4; h++) {
        const int i4 = tid + h * 256;
        float4 s = make_float4(0.f, 0.f, 0.f, 0.f);
#pragma unroll 8
        for (int cc = 0; cc < CHUNKS; cc++) {
            float4 v = pbase[(size_t)cc * (2 * Fn * Tn / 4) + i4];
            s.x += v.x; s.y += v.y; s.z += v.z; s.w += v.w;
        }
        ((float4*)LsRs)[i4] = s;
    }
    // V_e transpose: VeT[t][u] = V_e[u][t]
#pragma unroll
    for (int h = 0; h < 4; h++) {
        int i = tid + h * 256;
        int u = i >> 5, t = i & 31;
        VeT[t * Tn + u] = V_e[u * Tn + t];
    }
    __syncthreads();

    // product + sigmoid: 1024 outputs, 4 per thread (t = lane, s = warp+8h)
    const float* Ls = LsRs;            // lhs1[f][t]
    const float* Rs = LsRs + Fn * Tn;  // R2[f][s]
#pragma unroll
    for (int h = 0; h < 4; h++) {
        const int t = lane;
        const int s = w + 8 * h;
        float p = 0.f;
#pragma unroll
        for (int f = 0; f < Fn; f++)
            p = fmaf(Ls[f * Tn + t], Rs[f * Tn + s], p);
        p += b_e[t * Tn + s];
        sig[s * Tn + t] = 1.f / (1.f + expf(-p));
    }
    __syncthreads();

    // E + column softmax over u (u = lane, s = warp+8h)
#pragma unroll
    for (int h = 0; h < 4; h++) {
        const int u = lane;
        const int s = w + 8 * h;
        float e = 0.f;
#pragma unroll
        for (int t = 0; t < Tn; t++)
            e = fmaf(VeT[t * Tn + u], sig[s * Tn + t], e);

        float m = e;
#pragma unroll
        for (int o = 16; o; o >>= 1)
            m = fmaxf(m, __shfl_xor_sync(0xffffffffu, m, o));
        float ex = expf(e - m);
        float ssum = ex;
#pragma unroll
        for (int o = 16; o; o >>= 1)
            ssum += __shfl_xor_sync(0xffffffffu, ssum, o);

        out[b * Tn * Tn + u * Tn + s] = ex / ssum;
    }
}

extern "C" void kernel_launch(void* const* d_in, const int* in_sizes, int n_in,
                              void* d_out, int out_size)
{
    const float* x   = (const float*)d_in[0];
    const float* U1  = (const float*)d_in[1];
    const float* U2  = (const float*)d_in[2];
    const float* U3  = (const float*)d_in[3];
    const float* b_e = (const float*)d_in[4];
    const float* V_e = (const float*)d_in[5];
    float* out = (float*)d_out;

    fused_kernel<<<NBLK, 256>>>(x, U1, U2, U3, b_e, V_e, out);
}

// round 8
// speedup vs baseline: 1.4996x; 1.4996x over previous
#include <cuda_runtime.h>
#include <cuda_bf16.h>
#include <math.h>

#define Bn 16
#define Nn 2048
#define Fn 64
#define Tn 32
#define CHUNKS 128             // chunks per batch
#define NC (Nn / CHUNKS)       // 16 nodes per chunk
#define NBLK (Bn * CHUNKS)     // 2048 reduce blocks
#define GROUPS 8               // chunk-groups for two-stage partial sum
#define CPG (CHUNKS / GROUPS)  // 16 chunks per group

// Partial accumulators: [block][0=lhs1,1=R2][f*t]  (32 MB)
__device__ float g_partial[NBLK][2][Fn * Tn];
// Group-level mids: [group][b][i]  (2 MB)
__device__ float g_mid[GROUPS][Bn][2 * Fn * Tn];

// ---------------------------------------------------------------------------
// Pass 1 (R4/R6 proven structure, occupancy 6): stream x once (256 MB).
// Barrier-free mainloop: all 16 nodes' loads pipeline, then ONE barrier,
// then the cross-warp r-reduction and R2 accumulation.
// Warp w owns f in [8w, 8w+8); lane = t. Coalesced 128B LDG.32.
// Distinct __shared__ arrays (NOT an aliased arena) so ptxas can batch loads.
// ---------------------------------------------------------------------------
__global__ __launch_bounds__(256, 6)
void reduce_kernel(const float* __restrict__ x,
                   const float* __restrict__ U1,
                   const float* __restrict__ U2,
                   const float* __restrict__ U3)
{
    const int blk  = blockIdx.x;        // 0..NBLK-1
    const int b    = blk >> 7;          // / CHUNKS
    const int c    = blk & (CHUNKS - 1);
    const int n0   = c * NC;
    const int tid  = threadIdx.x;
    const int w    = tid >> 5;          // warp 0..7
    const int lane = tid & 31;          // = t

    __shared__ float U2s[NC][Fn];       // U2s[nn][f] = U2[f*N + n0+nn]
    __shared__ float U3s[Fn];
    __shared__ float U1s[NC];
    __shared__ float red[NC][8][32];    // warp-partials of r  (16 KB)
    __shared__ float rsum[NC][32];      // reduced r           (2 KB)

    if (tid < Fn) U3s[tid] = U3[tid];
    if (tid < NC) U1s[tid] = U1[n0 + tid];
    for (int i = tid; i < NC * Fn; i += 256) {
        int f  = i >> 4;                // i / NC  (NC == 16)
        int nn = i & (NC - 1);
        U2s[nn][f] = U2[f * Nn + n0 + nn];
    }
    __syncthreads();

    float accL[8];
#pragma unroll
    for (int j = 0; j < 8; j++) accL[j] = 0.f;

    const float* xb = x + ((size_t)b * Nn + n0) * (Fn * Tn);
    const int fbase = w * 8;
    float u3r[8];
#pragma unroll
    for (int j = 0; j < 8; j++) u3r[j] = U3s[fbase + j];

    // ---- Phase A: barrier-free streaming ----
#pragma unroll 2
    for (int nn = 0; nn < NC; nn++) {
        const float* xn = xb + (size_t)nn * (Fn * Tn) + fbase * Tn + lane;
        float v[8];
#pragma unroll
        for (int j = 0; j < 8; j++)
            v[j] = xn[j * Tn];

        const float u1n = U1s[nn];
        float r = 0.f;
#pragma unroll
        for (int j = 0; j < 8; j++) {
            accL[j] = fmaf(u1n, v[j], accL[j]);
            r = fmaf(u3r[j], v[j], r);
        }
        red[nn][w][lane] = r;
    }
    __syncthreads();

    // ---- Phase B: reduce r across warps, then R2 accumulation ----
#pragma unroll
    for (int h = 0; h < 2; h++) {
        int i  = tid + h * 256;
        int nn = i >> 5;
        int t  = i & 31;
        float s = 0.f;
#pragma unroll
        for (int w2 = 0; w2 < 8; w2++) s += red[nn][w2][t];
        rsum[nn][t] = s;
    }
    __syncthreads();

    float accR[8];
#pragma unroll
    for (int j = 0; j < 8; j++) accR[j] = 0.f;
#pragma unroll
    for (int nn = 0; nn < NC; nn++) {
        const float rt = rsum[nn][lane];
#pragma unroll
        for (int j = 0; j < 8; j++)
            accR[j] = fmaf(U2s[nn][fbase + j], rt, accR[j]);
    }

    float* pl = &g_partial[blk][0][0];
    float* pr = &g_partial[blk][1][0];
#pragma unroll
    for (int j = 0; j < 8; j++) {
        pl[(fbase + j) * Tn + lane] = accL[j];
        pr[(fbase + j) * Tn + lane] = accR[j];
    }
}

// ---------------------------------------------------------------------------
// Pass 1.5: stage-1 partial sum. 131072 threads; thread (g,b,i4) sums 16
// chunks of one float4 (LDG.128). 8x thread parallelism vs single-stage.
// ---------------------------------------------------------------------------
__global__ __launch_bounds__(256)
void sum_partials()
{
    const int idx = blockIdx.x * 256 + threadIdx.x;  // 0..131071
    const int g  = idx >> 14;          // group 0..7
    const int b  = (idx >> 10) & 15;   // batch
    const int i4 = idx & 1023;         // float4 index within 4096 floats

    const float4* p = (const float4*)(&g_partial[b * CHUNKS + g * CPG][0][0]) + i4;
    float4 s = make_float4(0.f, 0.f, 0.f, 0.f);
#pragma unroll 8
    for (int c = 0; c < CPG; c++) {
        float4 v = p[(size_t)c * (2 * Fn * Tn / 4)];
        s.x += v.x; s.y += v.y; s.z += v.z; s.w += v.w;
    }
    ((float4*)&g_mid[g][b][0])[i4] = s;
}

// ---------------------------------------------------------------------------
// Pass 2: per-batch epilogue (grid = B, 1024 threads). Sums the 8 group
// mids inline, then product->sigmoid->V_e->column softmax. Tiny.
// ---------------------------------------------------------------------------
__global__ __launch_bounds__(1024, 1)
void epilogue_kernel(const float* __restrict__ b_e,
                     const float* __restrict__ V_e,
                     float* __restrict__ out)
{
    const int b   = blockIdx.x;
    const int tid = threadIdx.x;

    __shared__ float Ls[Fn * Tn];      // lhs1[f][t]
    __shared__ float Rs[Fn * Tn];      // R2[f][s]
    __shared__ float sig_sh[Tn * Tn];  // sig[s][t]
    __shared__ float VeT[Tn * Tn];     // V_e transposed: VeT[t][u]

    for (int i = tid; i < Fn * Tn; i += 1024) {
        float sL = 0.f, sR = 0.f;
#pragma unroll
        for (int g = 0; g < GROUPS; g++) {
            sL += g_mid[g][b][i];
            sR += g_mid[g][b][Fn * Tn + i];
        }
        Ls[i] = sL;
        Rs[i] = sR;
    }
    {
        int u = tid >> 5, t = tid & 31;
        VeT[t * Tn + u] = V_e[u * Tn + t];
    }
    __syncthreads();

    // product + sigmoid: thread = (t = lane, s = warp)
    {
        const int t = tid & 31;
        const int s = tid >> 5;
        float p = 0.f;
#pragma unroll
        for (int f = 0; f < Fn; f++)
            p = fmaf(Ls[f * Tn + t], Rs[f * Tn + s], p);
        p += b_e[t * Tn + s];
        sig_sh[s * Tn + t] = 1.f / (1.f + expf(-p));
    }
    __syncthreads();

    // E + column softmax over u: thread = (u = lane, s = warp)
    {
        const int u = tid & 31;
        const int s = tid >> 5;
        float e = 0.f;
#pragma unroll
        for (int t = 0; t < Tn; t++)
            e = fmaf(VeT[t * Tn + u], sig_sh[s * Tn + t], e);

        float m = e;
#pragma unroll
        for (int o = 16; o; o >>= 1)
            m = fmaxf(m, __shfl_xor_sync(0xffffffffu, m, o));
        float ex = expf(e - m);
        float ssum = ex;
#pragma unroll
        for (int o = 16; o; o >>= 1)
            ssum += __shfl_xor_sync(0xffffffffu, ssum, o);

        out[b * Tn * Tn + u * Tn + s] = ex / ssum;
    }
}

extern "C" void kernel_launch(void* const* d_in, const int* in_sizes, int n_in,
                              void* d_out, int out_size)
{
    const float* x   = (const float*)d_in[0];
    const float* U1  = (const float*)d_in[1];
    const float* U2  = (const float*)d_in[2];
    const float* U3  = (const float*)d_in[3];
    const float* b_e = (const float*)d_in[4];
    const float* V_e = (const float*)d_in[5];
    float* out = (float*)d_out;

    reduce_kernel<<<NBLK, 256>>>(x, U1, U2, U3);
    sum_partials<<<(GROUPS * Bn * 2 * Fn * Tn / 4) / 256, 256>>>();
    epilogue_kernel<<<Bn, 1024>>>(b_e, V_e, out);
}

// round 9
// speedup vs baseline: 1.8186x; 1.2128x over previous
#include <cuda_runtime.h>
#include <cuda_bf16.h>
#include <math.h>

#define Bn 16
#define Nn 2048
#define Fn 64
#define Tn 32
#define CHUNKS 128             // chunks per batch
#define NC (Nn / CHUNKS)       // 16 nodes per chunk
#define NBLK (Bn * CHUNKS)     // 2048 reduce blocks

// Final sums, accumulated by atomics: [b][0=lhs1,1=R2][f*t]  (256 KB)
// Zero at module load; epilogue re-zeroes after consuming -> replay-safe.
__device__ float g_sum[Bn][2 * Fn * Tn];

// ---------------------------------------------------------------------------
// Pass 1 (R6-proven mainloop, occupancy 5): stream x once (256 MB).
// Barrier-free over all 16 nodes, one barrier, cross-warp r-reduction,
// R2 accumulation. Finishes with REDG atomic adds into g_sum (no partial
// buffer, no readback).
// Warp w owns f in [8w, 8w+8); lane = t. Coalesced 128B LDG.32.
// ---------------------------------------------------------------------------
__global__ __launch_bounds__(256, 5)
void reduce_kernel(const float* __restrict__ x,
                   const float* __restrict__ U1,
                   const float* __restrict__ U2,
                   const float* __restrict__ U3)
{
    const int blk  = blockIdx.x;        // 0..NBLK-1
    const int b    = blk >> 7;          // / CHUNKS
    const int c    = blk & (CHUNKS - 1);
    const int n0   = c * NC;
    const int tid  = threadIdx.x;
    const int w    = tid >> 5;          // warp 0..7
    const int lane = tid & 31;          // = t

    __shared__ float U2s[NC][Fn];       // U2s[nn][f] = U2[f*N + n0+nn]
    __shared__ float U3s[Fn];
    __shared__ float U1s[NC];
    __shared__ float red[NC][8][32];    // warp-partials of r  (16 KB)
    __shared__ float rsum[NC][32];      // reduced r           (2 KB)

    if (tid < Fn) U3s[tid] = U3[tid];
    if (tid < NC) U1s[tid] = U1[n0 + tid];
    for (int i = tid; i < NC * Fn; i += 256) {
        int f  = i >> 4;                // i / NC  (NC == 16)
        int nn = i & (NC - 1);
        U2s[nn][f] = U2[f * Nn + n0 + nn];
    }
    __syncthreads();

    float accL[8];
#pragma unroll
    for (int j = 0; j < 8; j++) accL[j] = 0.f;

    const float* xb = x + ((size_t)b * Nn + n0) * (Fn * Tn);
    const int fbase = w * 8;
    float u3r[8];
#pragma unroll
    for (int j = 0; j < 8; j++) u3r[j] = U3s[fbase + j];

    // ---- Phase A: barrier-free streaming over 16 nodes ----
#pragma unroll 2
    for (int nn = 0; nn < NC; nn++) {
        const float* xn = xb + (size_t)nn * (Fn * Tn) + fbase * Tn + lane;
        float v[8];
#pragma unroll
        for (int j = 0; j < 8; j++)
            v[j] = xn[j * Tn];

        const float u1n = U1s[nn];
        float r = 0.f;
#pragma unroll
        for (int j = 0; j < 8; j++) {
            accL[j] = fmaf(u1n, v[j], accL[j]);
            r = fmaf(u3r[j], v[j], r);
        }
        red[nn][w][lane] = r;
    }
    __syncthreads();

    // ---- Phase B: reduce r across warps, then R2 accumulation ----
#pragma unroll
    for (int h = 0; h < 2; h++) {
        int i  = tid + h * 256;
        int nn = i >> 5;
        int t  = i & 31;
        float s = 0.f;
#pragma unroll
        for (int w2 = 0; w2 < 8; w2++) s += red[nn][w2][t];
        rsum[nn][t] = s;
    }
    __syncthreads();

    float accR[8];
#pragma unroll
    for (int j = 0; j < 8; j++) accR[j] = 0.f;
#pragma unroll
    for (int nn = 0; nn < NC; nn++) {
        const float rt = rsum[nn][lane];
#pragma unroll
        for (int j = 0; j < 8; j++)
            accR[j] = fmaf(U2s[nn][fbase + j], rt, accR[j]);
    }

    // ---- Commit: REDG atomic accumulation into the 256 KB g_sum ----
    float* gl = &g_sum[b][0];
    float* gr = &g_sum[b][Fn * Tn];
#pragma unroll
    for (int j = 0; j < 8; j++) {
        atomicAdd(gl + (fbase + j) * Tn + lane, accL[j]);
        atomicAdd(gr + (fbase + j) * Tn + lane, accR[j]);
    }
}

// ---------------------------------------------------------------------------
// Pass 2: per-batch epilogue (grid = B, 1024 threads). Reads g_sum (L2-hot),
// RE-ZEROES it for the next graph replay, then product -> sigmoid -> V_e ->
// column softmax.
// ---------------------------------------------------------------------------
__global__ __launch_bounds__(1024, 1)
void epilogue_kernel(const float* __restrict__ b_e,
                     const float* __restrict__ V_e,
                     float* __restrict__ out)
{
    const int b   = blockIdx.x;
    const int tid = threadIdx.x;

    __shared__ float Ls[Fn * Tn];      // lhs1[f][t]
    __shared__ float Rs[Fn * Tn];      // R2[f][s]
    __shared__ float sig_sh[Tn * Tn];  // sig[s][t]
    __shared__ float VeT[Tn * Tn];     // V_e transposed: VeT[t][u]

    for (int i = tid; i < Fn * Tn; i += 1024) {
        Ls[i] = g_sum[b][i];
        Rs[i] = g_sum[b][Fn * Tn + i];
        g_sum[b][i] = 0.f;             // self-clean for next replay
        g_sum[b][Fn * Tn + i] = 0.f;
    }
    {
        int u = tid >> 5, t = tid & 31;
        VeT[t * Tn + u] = V_e[u * Tn + t];
    }
    __syncthreads();

    // product + sigmoid: thread = (t = lane, s = warp)
    {
        const int t = tid & 31;
        const int s = tid >> 5;
        float p = 0.f;
#pragma unroll
        for (int f = 0; f < Fn; f++)
            p = fmaf(Ls[f * Tn + t], Rs[f * Tn + s], p);
        p += b_e[t * Tn + s];
        sig_sh[s * Tn + t] = 1.f / (1.f + expf(-p));
    }
    __syncthreads();

    // E + column softmax over u: thread = (u = lane, s = warp)
    {
        const int u = tid & 31;
        const int s = tid >> 5;
        float e = 0.f;
#pragma unroll
        for (int t = 0; t < Tn; t++)
            e = fmaf(VeT[t * Tn + u], sig_sh[s * Tn + t], e);

        float m = e;
#pragma unroll
        for (int o = 16; o; o >>= 1)
            m = fmaxf(m, __shfl_xor_sync(0xffffffffu, m, o));
        float ex = expf(e - m);
        float ssum = ex;
#pragma unroll
        for (int o = 16; o; o >>= 1)
            ssum += __shfl_xor_sync(0xffffffffu, ssum, o);

        out[b * Tn * Tn + u * Tn + s] = ex / ssum;
    }
}

extern "C" void kernel_launch(void* const* d_in, const int* in_sizes, int n_in,
                              void* d_out, int out_size)
{
    const float* x   = (const float*)d_in[0];
    const float* U1  = (const float*)d_in[1];
    const float* U2  = (const float*)d_in[2];
    const float* U3  = (const float*)d_in[3];
    const float* b_e = (const float*)d_in[4];
    const float* V_e = (const float*)d_in[5];
    float* out = (float*)d_out;

    reduce_kernel<<<NBLK, 256>>>(x, U1, U2, U3);
    epilogue_kernel<<<Bn, 1024>>>(b_e, V_e, out);
}